// round 1
// baseline (speedup 1.0000x reference)
#include <cuda_runtime.h>
#include <math.h>

#define B_ROWS 8192
#define DIM    4096
#define NBLK   64
#define BLK    64
#define EPS    1e-6f

// ---------------- scratch (module-scope device globals; no allocation) ------
__device__ float g_h[(size_t)B_ROWS * DIM];        // 128 MiB intermediate h
__device__ float g_psum[32 * DIM];                 // partial column sums
__device__ float g_psumsq[32 * DIM];               // partial column sum-of-squares
__device__ float g_mean[DIM];
__device__ float g_scale[DIM];                     // tree_scale^2 = 1/(std+eps)

// ---------------- GEMM: h = x @ W + x_init ---------------------------------
// W is block upper-triangular in 64x64 blocks:
//   diag block (kb==cb): tw*tw ; upper (kb<cb): bbw ; lower: 0 (skipped).
#define BM 128
#define BN 64
#define BK 16
#define TM 8
#define TN 4

__global__ __launch_bounds__(256) void gemm_kernel(
    const float* __restrict__ x,
    const float* __restrict__ x_init,
    const float* __restrict__ tw,
    const float* __restrict__ bbw)
{
    const int cb = blockIdx.x;            // output column tile == 64-col block id
    const int mt = blockIdx.y;
    const int m0 = mt * BM;
    const int n0 = cb * BN;

    __shared__ float As[BK][BM];          // A transposed: As[k][m]
    __shared__ float Bs[BK][BN];

    const int tid = threadIdx.x;
    const int tx  = tid & 15;             // 0..15 -> 4 output cols each
    const int ty  = tid >> 4;             // 0..15 -> 8 output rows each

    float acc[TM][TN];
    #pragma unroll
    for (int i = 0; i < TM; i++)
        #pragma unroll
        for (int j = 0; j < TN; j++)
            acc[i][j] = 0.0f;

    const int ktiles    = (cb + 1) * (BLK / BK);   // only blocks kb <= cb
    const int diag_tile = cb * (BLK / BK);         // tiles >= this are diagonal block

    for (int kt = 0; kt < ktiles; kt++) {
        const int  k0   = kt * BK;
        const bool diag = (kt >= diag_tile);

        // --- load A tile: 128 rows x 16 k, as 512 float4, 2 per thread ---
        #pragma unroll
        for (int r = 0; r < 2; r++) {
            const int f   = tid + r * 256;
            const int row = f >> 2;           // 0..127
            const int c4  = (f & 3) * 4;      // 0,4,8,12
            const float4 v = *(const float4*)(x + (size_t)(m0 + row) * DIM + k0 + c4);
            As[c4 + 0][row] = v.x;
            As[c4 + 1][row] = v.y;
            As[c4 + 2][row] = v.z;
            As[c4 + 3][row] = v.w;
        }
        // --- load B tile: 16 k-rows x 64 cols, 1 float4 per thread ---
        {
            const int row = tid >> 4;         // 0..15
            const int c4  = (tid & 15) * 4;   // 0..60
            const float* src = diag ? tw : bbw;
            float4 v = *(const float4*)(src + (size_t)(k0 + row) * DIM + n0 + c4);
            if (diag) { v.x *= v.x; v.y *= v.y; v.z *= v.z; v.w *= v.w; }
            *(float4*)&Bs[row][c4] = v;
        }
        __syncthreads();

        #pragma unroll
        for (int k = 0; k < BK; k++) {
            const float4 a0 = *(const float4*)&As[k][ty * TM];
            const float4 a1 = *(const float4*)&As[k][ty * TM + 4];
            const float4 b  = *(const float4*)&Bs[k][tx * TN];
            const float am[TM] = {a0.x, a0.y, a0.z, a0.w, a1.x, a1.y, a1.z, a1.w};
            const float bn[TN] = {b.x, b.y, b.z, b.w};
            #pragma unroll
            for (int i = 0; i < TM; i++)
                #pragma unroll
                for (int j = 0; j < TN; j++)
                    acc[i][j] = fmaf(am[i], bn[j], acc[i][j]);
        }
        __syncthreads();
    }

    // --- epilogue: add x_init, store h ---
    #pragma unroll
    for (int i = 0; i < TM; i++) {
        const int gm = m0 + ty * TM + i;
        const size_t off = (size_t)gm * DIM + n0 + tx * TN;
        const float4 xi = *(const float4*)(x_init + off);
        float4 o;
        o.x = acc[i][0] + xi.x;
        o.y = acc[i][1] + xi.y;
        o.z = acc[i][2] + xi.z;
        o.w = acc[i][3] + xi.w;
        *(float4*)(g_h + off) = o;
    }
}

// ---------------- stats stage 1: deterministic partial column sums ----------
// grid (16 col-groups, 32 row-groups), 256 threads. Thread owns 1 column,
// sums 256 rows. Fixed output slot -> bitwise deterministic.
__global__ __launch_bounds__(256) void stats1_kernel()
{
    const int col = blockIdx.x * 256 + threadIdx.x;   // 0..4095
    const int rg  = blockIdx.y;                        // 0..31
    const int r0  = rg * 256;
    float s = 0.0f, q = 0.0f;
    const float* p = g_h + (size_t)r0 * DIM + col;
    #pragma unroll 8
    for (int r = 0; r < 256; r++) {
        const float v = p[(size_t)r * DIM];
        s += v;
        q = fmaf(v, v, q);
    }
    g_psum[rg * DIM + col]   = s;
    g_psumsq[rg * DIM + col] = q;
}

// ---------------- stats stage 2: finalize mean / scale ----------------------
__global__ __launch_bounds__(256) void stats2_kernel()
{
    const int col = blockIdx.x * 256 + threadIdx.x;   // 0..4095
    float s = 0.0f, q = 0.0f;
    #pragma unroll
    for (int rg = 0; rg < 32; rg++) {
        s += g_psum[rg * DIM + col];
        q += g_psumsq[rg * DIM + col];
    }
    const float inv_n = 1.0f / (float)B_ROWS;
    const float mean  = s * inv_n;
    float var = q * inv_n - mean * mean;
    var = fmaxf(var, 0.0f);
    const float stdv = sqrtf(var);
    g_mean[col]  = mean;
    g_scale[col] = 1.0f / (stdv + EPS);   // (sqrt(1/(std+eps)))^2
}

// ---------------- normalize + sigmoid ---------------------------------------
__global__ __launch_bounds__(256) void final_kernel(float* __restrict__ out)
{
    const int row  = blockIdx.y;                          // 0..8191
    const int col4 = blockIdx.x * 256 + threadIdx.x;      // 0..1023
    const int col  = col4 * 4;
    const size_t off = (size_t)row * DIM + col;

    const float4 h  = *(const float4*)(g_h + off);
    const float4 mu = *(const float4*)(g_mean + col);
    const float4 sc = *(const float4*)(g_scale + col);

    float4 o;
    o.x = 1.0f / (1.0f + expf(-(h.x - mu.x) * sc.x));
    o.y = 1.0f / (1.0f + expf(-(h.y - mu.y) * sc.y));
    o.z = 1.0f / (1.0f + expf(-(h.z - mu.z) * sc.z));
    o.w = 1.0f / (1.0f + expf(-(h.w - mu.w) * sc.w));
    *(float4*)(out + off) = o;
}

// ---------------- launcher ---------------------------------------------------
extern "C" void kernel_launch(void* const* d_in, const int* in_sizes, int n_in,
                              void* d_out, int out_size)
{
    const float* x   = (const float*)d_in[0];
    const float* xi  = (const float*)d_in[1];
    const float* tw  = (const float*)d_in[2];
    const float* bbw = (const float*)d_in[3];
    float* out = (float*)d_out;

    gemm_kernel<<<dim3(DIM / BN, B_ROWS / BM), 256>>>(x, xi, tw, bbw);
    stats1_kernel<<<dim3(DIM / 256, 32), 256>>>();
    stats2_kernel<<<DIM / 256, 256>>>();
    final_kernel<<<dim3(DIM / (256 * 4), B_ROWS), 256>>>(out);
}

// round 3
// speedup vs baseline: 1.3374x; 1.3374x over previous
#include <cuda_runtime.h>
#include <cstdint>
#include <math.h>

#define DIM    4096
#define B_ROWS 8192
#define EPS    1e-6f

// GEMM tiling
#define BM 128
#define BN 128
#define BK 32
#define NT 32                 // column tiles
#define MT 64                 // row tiles
#define ROWPAD 36             // floats per smem row (144B, 16B aligned)
#define TILE_F (128 * ROWPAD)            // floats per operand tile (4608)
#define STAGE_F (4 * TILE_F)             // 4 tiles per stage (18432 floats)
#define DYN_SMEM (2 * STAGE_F * 4)       // bytes (147456)

// ---------------- scratch (device globals; no runtime allocation) ----------
__device__ float g_h[(size_t)B_ROWS * DIM];
__device__ float g_xhi[(size_t)B_ROWS * DIM];
__device__ float g_xlo[(size_t)B_ROWS * DIM];
__device__ float g_whiT[(size_t)DIM * DIM];    // W^T hi: [n][k], masked, diag squared
__device__ float g_wloT[(size_t)DIM * DIM];    // W^T lo
__device__ float g_psum[32 * DIM];
__device__ float g_psumsq[32 * DIM];
__device__ float g_mean[DIM];
__device__ float g_scale[DIM];

// ---------------- helpers ---------------------------------------------------
__device__ __forceinline__ uint32_t smem_u32(const void* p) {
    uint32_t a;
    asm("{ .reg .u64 t; cvta.to.shared.u64 t, %1; cvt.u32.u64 %0, t; }"
        : "=r"(a) : "l"(p));
    return a;
}

__device__ __forceinline__ float tf32r(float v) {
    uint32_t u;
    asm("cvt.rna.tf32.f32 %0, %1;" : "=r"(u) : "f"(v));
    return __uint_as_float(u);
}

#define CPA16(dst, src) \
    asm volatile("cp.async.cg.shared.global [%0], [%1], 16;" :: "r"(dst), "l"(src) : "memory")
#define CPA_COMMIT() asm volatile("cp.async.commit_group;" ::: "memory")
#define CPA_WAIT1()  asm volatile("cp.async.wait_group 1;" ::: "memory")
#define CPA_WAIT0()  asm volatile("cp.async.wait_group 0;" ::: "memory")

__device__ __forceinline__ void mma_tf32(float* c, const float* a, const float* b) {
    asm volatile(
        "mma.sync.aligned.m16n8k8.row.col.f32.tf32.tf32.f32 "
        "{%0,%1,%2,%3}, {%4,%5,%6,%7}, {%8,%9}, {%0,%1,%2,%3};"
        : "+f"(c[0]), "+f"(c[1]), "+f"(c[2]), "+f"(c[3])
        : "r"(__float_as_uint(a[0])), "r"(__float_as_uint(a[1])),
          "r"(__float_as_uint(a[2])), "r"(__float_as_uint(a[3])),
          "r"(__float_as_uint(b[0])), "r"(__float_as_uint(b[1])));
}

// ---------------- prologue 1: split x into tf32 hi/lo -----------------------
__global__ __launch_bounds__(256) void split_x_kernel(const float4* __restrict__ x)
{
    const size_t i = (size_t)blockIdx.x * 256 + threadIdx.x;
    const float4 v = x[i];
    float4 h, l;
    h.x = tf32r(v.x); l.x = tf32r(v.x - h.x);
    h.y = tf32r(v.y); l.y = tf32r(v.y - h.y);
    h.z = tf32r(v.z); l.z = tf32r(v.z - h.z);
    h.w = tf32r(v.w); l.w = tf32r(v.w - h.w);
    ((float4*)g_xhi)[i] = h;
    ((float4*)g_xlo)[i] = l;
}

// ---------------- prologue 2: build W^T (masked, squared diag), split hi/lo -
__global__ __launch_bounds__(256) void split_w_kernel(
    const float* __restrict__ tw, const float* __restrict__ bbw)
{
    __shared__ float shi[32][33];
    __shared__ float slo[32][33];
    const int tx = threadIdx.x & 31;
    const int ty = threadIdx.x >> 5;           // 0..7
    const int k0 = blockIdx.y * 32;
    const int n0 = blockIdx.x * 32;

    #pragma unroll
    for (int r = 0; r < 4; r++) {
        const int k = k0 + ty + r * 8;
        const int n = n0 + tx;
        const int kb = k >> 6, nb = n >> 6;
        float w = 0.0f;
        if (kb == nb)      { const float t = tw[(size_t)k * DIM + n]; w = t * t; }
        else if (kb < nb)  { w = bbw[(size_t)k * DIM + n]; }
        const float h = tf32r(w);
        const float l = tf32r(w - h);
        shi[ty + r * 8][tx] = h;
        slo[ty + r * 8][tx] = l;
    }
    __syncthreads();
    #pragma unroll
    for (int r = 0; r < 4; r++) {
        const int n = n0 + ty + r * 8;
        const int k = k0 + tx;
        g_whiT[(size_t)n * DIM + k] = shi[tx][ty + r * 8];
        g_wloT[(size_t)n * DIM + k] = slo[tx][ty + r * 8];
    }
}

// ---------------- 3xTF32 mma.sync GEMM: h = x @ W + x_init ------------------
// Grid (NT, MT). CTA 128x128, BK=32, 2-stage cp.async pipeline.
// Warp (wid>>2 = m half, wid&3 = n quarter): 64x32 warp tile.
__global__ __launch_bounds__(256, 1) void gemm_mma_kernel(const float* __restrict__ x_init)
{
    extern __shared__ float sm[];
    const uint32_t smb = smem_u32(sm);

    const int tid = threadIdx.x;
    const int wid = tid >> 5;
    const int lid = tid & 31;
    const int lane4 = lid >> 2;     // 0..7
    const int laneq = lid & 3;      // 0..3

    const int nt = blockIdx.x;
    const int mt = blockIdx.y;
    const int m0 = mt * BM;
    const int n0 = nt * BN;
    const int KT = (nt + 1) * 4;    // k-tiles of 32

    const int m0w = (wid >> 2) * 64;
    const int n0w = (wid & 3) * 32;

    float c[4][4][4];
    #pragma unroll
    for (int i = 0; i < 4; i++)
        #pragma unroll
        for (int j = 0; j < 4; j++)
            #pragma unroll
            for (int q = 0; q < 4; q++)
                c[i][j][q] = 0.0f;

    // producer: 16 cp.async (16B) per thread per stage
    // p -> tile (0:Ahi 1:Alo 2:Bhi 3:Blo), row (0..127), chunk (0..7)
    auto issue_stage = [&](int kt, int s) {
        const int kof = kt * BK;
        const uint32_t sb = smb + (uint32_t)s * (STAGE_F * 4);
        #pragma unroll
        for (int it = 0; it < 16; it++) {
            const int p    = tid + it * 256;
            const int tile = p >> 10;
            const int q    = p & 1023;
            const int row  = q >> 3;
            const int ch   = q & 7;
            const float* base;
            int row0;
            if      (tile == 0) { base = g_xhi;  row0 = m0; }
            else if (tile == 1) { base = g_xlo;  row0 = m0; }
            else if (tile == 2) { base = g_whiT; row0 = n0; }
            else                { base = g_wloT; row0 = n0; }
            const float* src = base + (size_t)(row0 + row) * DIM + kof + ch * 4;
            const uint32_t dst = sb + (uint32_t)(tile * (TILE_F * 4) + row * (ROWPAD * 4) + ch * 16);
            CPA16(dst, src);
        }
        CPA_COMMIT();
    };

    issue_stage(0, 0);

    for (int kt = 0; kt < KT; kt++) {
        const int s = kt & 1;
        if (kt + 1 < KT) { issue_stage(kt + 1, s ^ 1); CPA_WAIT1(); }
        else             { CPA_WAIT0(); }
        __syncthreads();

        const float* sAh = sm + s * STAGE_F;
        const float* sAl = sAh + TILE_F;
        const float* sBh = sAl + TILE_F;
        const float* sBl = sBh + TILE_F;

        #pragma unroll
        for (int ks = 0; ks < 4; ks++) {
            const int k0 = ks * 8 + laneq;

            float ah[4][4], al[4][4];
            #pragma unroll
            for (int i = 0; i < 4; i++) {
                const int r = (m0w + i * 16 + lane4) * ROWPAD + k0;
                ah[i][0] = sAh[r];
                ah[i][1] = sAh[r + 8 * ROWPAD];
                ah[i][2] = sAh[r + 4];
                ah[i][3] = sAh[r + 8 * ROWPAD + 4];
                al[i][0] = sAl[r];
                al[i][1] = sAl[r + 8 * ROWPAD];
                al[i][2] = sAl[r + 4];
                al[i][3] = sAl[r + 8 * ROWPAD + 4];
            }
            float bh[4][2], bl[4][2];
            #pragma unroll
            for (int j = 0; j < 4; j++) {
                const int rc = (n0w + j * 8 + lane4) * ROWPAD + k0;
                bh[j][0] = sBh[rc];
                bh[j][1] = sBh[rc + 4];
                bl[j][0] = sBl[rc];
                bl[j][1] = sBl[rc + 4];
            }
            #pragma unroll
            for (int i = 0; i < 4; i++)
                #pragma unroll
                for (int j = 0; j < 4; j++) {
                    mma_tf32(c[i][j], ah[i], bh[j]);
                    mma_tf32(c[i][j], al[i], bh[j]);
                    mma_tf32(c[i][j], ah[i], bl[j]);
                }
        }
        __syncthreads();
    }

    // epilogue: += x_init, store h
    #pragma unroll
    for (int i = 0; i < 4; i++) {
        const int row = m0 + m0w + i * 16 + lane4;
        #pragma unroll
        for (int j = 0; j < 4; j++) {
            const int col = n0 + n0w + j * 8 + laneq * 2;
            const size_t o0 = (size_t)row * DIM + col;
            const size_t o1 = (size_t)(row + 8) * DIM + col;
            const float2 x0 = *(const float2*)(x_init + o0);
            const float2 x1 = *(const float2*)(x_init + o1);
            float2 v0, v1;
            v0.x = c[i][j][0] + x0.x;
            v0.y = c[i][j][1] + x0.y;
            v1.x = c[i][j][2] + x1.x;
            v1.y = c[i][j][3] + x1.y;
            *(float2*)(g_h + o0) = v0;
            *(float2*)(g_h + o1) = v1;
        }
    }
}

// ---------------- stats stage 1: deterministic partial column sums ----------
__global__ __launch_bounds__(256) void stats1_kernel()
{
    const int col = blockIdx.x * 256 + threadIdx.x;
    const int rg  = blockIdx.y;
    const int r0  = rg * 256;
    float s = 0.0f, q = 0.0f;
    const float* p = g_h + (size_t)r0 * DIM + col;
    #pragma unroll 8
    for (int r = 0; r < 256; r++) {
        const float v = p[(size_t)r * DIM];
        s += v;
        q = fmaf(v, v, q);
    }
    g_psum[rg * DIM + col]   = s;
    g_psumsq[rg * DIM + col] = q;
}

// ---------------- stats stage 2: finalize mean / scale ----------------------
__global__ __launch_bounds__(256) void stats2_kernel()
{
    const int col = blockIdx.x * 256 + threadIdx.x;
    float s = 0.0f, q = 0.0f;
    #pragma unroll
    for (int rg = 0; rg < 32; rg++) {
        s += g_psum[rg * DIM + col];
        q += g_psumsq[rg * DIM + col];
    }
    const float inv_n = 1.0f / (float)B_ROWS;
    const float mean  = s * inv_n;
    float var = q * inv_n - mean * mean;
    var = fmaxf(var, 0.0f);
    g_mean[col]  = mean;
    g_scale[col] = 1.0f / (sqrtf(var) + EPS);
}

// ---------------- normalize + sigmoid ---------------------------------------
__global__ __launch_bounds__(256) void final_kernel(float* __restrict__ out)
{
    const int row  = blockIdx.y;
    const int col  = (blockIdx.x * 256 + threadIdx.x) * 4;
    const size_t off = (size_t)row * DIM + col;

    const float4 h  = *(const float4*)(g_h + off);
    const float4 mu = *(const float4*)(g_mean + col);
    const float4 sc = *(const float4*)(g_scale + col);

    float4 o;
    o.x = 1.0f / (1.0f + expf(-(h.x - mu.x) * sc.x));
    o.y = 1.0f / (1.0f + expf(-(h.y - mu.y) * sc.y));
    o.z = 1.0f / (1.0f + expf(-(h.z - mu.z) * sc.z));
    o.w = 1.0f / (1.0f + expf(-(h.w - mu.w) * sc.w));
    *(float4*)(out + off) = o;
}

// ---------------- launcher ---------------------------------------------------
extern "C" void kernel_launch(void* const* d_in, const int* in_sizes, int n_in,
                              void* d_out, int out_size)
{
    const float* x   = (const float*)d_in[0];
    const float* xi  = (const float*)d_in[1];
    const float* tw  = (const float*)d_in[2];
    const float* bbw = (const float*)d_in[3];
    float* out = (float*)d_out;

    cudaFuncSetAttribute(gemm_mma_kernel,
                         cudaFuncAttributeMaxDynamicSharedMemorySize, DYN_SMEM);

    split_x_kernel<<<(B_ROWS * DIM) / (256 * 4), 256>>>((const float4*)x);
    split_w_kernel<<<dim3(DIM / 32, DIM / 32), 256>>>(tw, bbw);
    gemm_mma_kernel<<<dim3(NT, MT), 256, DYN_SMEM>>>(xi);
    stats1_kernel<<<dim3(DIM / 256, 32), 256>>>();
    stats2_kernel<<<DIM / 256, 256>>>();
    final_kernel<<<dim3(DIM / (256 * 4), B_ROWS), 256>>>(out);
}

// round 4
// speedup vs baseline: 1.9668x; 1.4706x over previous
#include <cuda_runtime.h>
#include <cstdint>
#include <math.h>

#define DIM    4096
#define B_ROWS 8192
#define EPS    1e-6f

// GEMM tiling
#define BM 128
#define BN 128
#define BK 32
#define NT 32                 // column tiles
#define MT 64                 // row tiles
#define ROWPAD 36             // floats per smem row (144B, 16B aligned)
#define TILE_F (128 * ROWPAD)            // floats per operand tile (4608)
#define STAGE_F (3 * TILE_F)             // 3 tiles per stage: Ah, Bh, Bl
#define DYN_SMEM (2 * STAGE_F * 4)       // 110592 bytes -> 2 CTAs/SM

// ---------------- scratch (device globals; no runtime allocation) ----------
__device__ float g_h[(size_t)B_ROWS * DIM];
__device__ float g_xhi[(size_t)B_ROWS * DIM];  // tf32-rounded x
__device__ float g_whiT[(size_t)DIM * DIM];    // W^T hi: [n][k], masked, diag squared
__device__ float g_wloT[(size_t)DIM * DIM];    // W^T lo (tf32 residual)
__device__ float g_psum[32 * DIM];
__device__ float g_psumsq[32 * DIM];
__device__ float g_mean[DIM];
__device__ float g_scale[DIM];

// ---------------- helpers ---------------------------------------------------
__device__ __forceinline__ uint32_t smem_u32(const void* p) {
    uint32_t a;
    asm("{ .reg .u64 t; cvta.to.shared.u64 t, %1; cvt.u32.u64 %0, t; }"
        : "=r"(a) : "l"(p));
    return a;
}

__device__ __forceinline__ float tf32r(float v) {
    uint32_t u;
    asm("cvt.rna.tf32.f32 %0, %1;" : "=r"(u) : "f"(v));
    return __uint_as_float(u);
}

#define CPA16(dst, src) \
    asm volatile("cp.async.cg.shared.global [%0], [%1], 16;" :: "r"(dst), "l"(src) : "memory")
#define CPA_COMMIT() asm volatile("cp.async.commit_group;" ::: "memory")
#define CPA_WAIT1()  asm volatile("cp.async.wait_group 1;" ::: "memory")
#define CPA_WAIT0()  asm volatile("cp.async.wait_group 0;" ::: "memory")

__device__ __forceinline__ void mma_tf32(float* c, const float* a, const float* b) {
    asm volatile(
        "mma.sync.aligned.m16n8k8.row.col.f32.tf32.tf32.f32 "
        "{%0,%1,%2,%3}, {%4,%5,%6,%7}, {%8,%9}, {%0,%1,%2,%3};"
        : "+f"(c[0]), "+f"(c[1]), "+f"(c[2]), "+f"(c[3])
        : "r"(__float_as_uint(a[0])), "r"(__float_as_uint(a[1])),
          "r"(__float_as_uint(a[2])), "r"(__float_as_uint(a[3])),
          "r"(__float_as_uint(b[0])), "r"(__float_as_uint(b[1])));
}

// ---------------- prologue 1: round x to tf32 (hi part only) ----------------
__global__ __launch_bounds__(256) void split_x_kernel(const float4* __restrict__ x)
{
    const size_t i = (size_t)blockIdx.x * 256 + threadIdx.x;
    const float4 v = x[i];
    float4 h;
    h.x = tf32r(v.x);
    h.y = tf32r(v.y);
    h.z = tf32r(v.z);
    h.w = tf32r(v.w);
    ((float4*)g_xhi)[i] = h;
}

// ---------------- prologue 2: build W^T (masked, squared diag), split hi/lo -
__global__ __launch_bounds__(256) void split_w_kernel(
    const float* __restrict__ tw, const float* __restrict__ bbw)
{
    __shared__ float shi[32][33];
    __shared__ float slo[32][33];
    const int tx = threadIdx.x & 31;
    const int ty = threadIdx.x >> 5;           // 0..7
    const int k0 = blockIdx.y * 32;
    const int n0 = blockIdx.x * 32;

    #pragma unroll
    for (int r = 0; r < 4; r++) {
        const int k = k0 + ty + r * 8;
        const int n = n0 + tx;
        const int kb = k >> 6, nb = n >> 6;
        float w = 0.0f;
        if (kb == nb)      { const float t = tw[(size_t)k * DIM + n]; w = t * t; }
        else if (kb < nb)  { w = bbw[(size_t)k * DIM + n]; }
        const float h = tf32r(w);
        const float l = tf32r(w - h);
        shi[ty + r * 8][tx] = h;
        slo[ty + r * 8][tx] = l;
    }
    __syncthreads();
    #pragma unroll
    for (int r = 0; r < 4; r++) {
        const int n = n0 + ty + r * 8;
        const int k = k0 + tx;
        g_whiT[(size_t)n * DIM + k] = shi[tx][ty + r * 8];
        g_wloT[(size_t)n * DIM + k] = slo[tx][ty + r * 8];
    }
}

// ---------------- 2xTF32 mma.sync GEMM: h = x @ W + x_init ------------------
// Grid (NT, MT). CTA 128x128, BK=32, 2-stage cp.async pipeline, 2 CTAs/SM.
// Warp (wid>>2 = m half, wid&3 = n quarter): 64x32 warp tile.
// Passes: c += Ah*Bh ; c += Ah*Bl   (x_lo term dropped; rel err ~2e-4)
__global__ __launch_bounds__(256, 2) void gemm_mma_kernel(const float* __restrict__ x_init)
{
    extern __shared__ float sm[];
    const uint32_t smb = smem_u32(sm);

    const int tid = threadIdx.x;
    const int wid = tid >> 5;
    const int lid = tid & 31;
    const int lane4 = lid >> 2;     // 0..7
    const int laneq = lid & 3;      // 0..3

    const int nt = (NT - 1) - blockIdx.x;   // heavy tiles first
    const int mt = blockIdx.y;
    const int m0 = mt * BM;
    const int n0 = nt * BN;
    const int KT = (nt + 1) * 4;    // k-tiles of 32

    const int m0w = (wid >> 2) * 64;
    const int n0w = (wid & 3) * 32;

    float c[4][4][4];
    #pragma unroll
    for (int i = 0; i < 4; i++)
        #pragma unroll
        for (int j = 0; j < 4; j++)
            #pragma unroll
            for (int q = 0; q < 4; q++)
                c[i][j][q] = 0.0f;

    // producer: 12 cp.async (16B) per thread per stage
    // p -> tile (0:Ah 1:Bh 2:Bl), row (0..127), chunk (0..7)
    auto issue_stage = [&](int kt, int s) {
        const int kof = kt * BK;
        const uint32_t sb = smb + (uint32_t)s * (STAGE_F * 4);
        #pragma unroll
        for (int it = 0; it < 12; it++) {
            const int p    = tid + it * 256;
            const int tile = p >> 10;
            const int q    = p & 1023;
            const int row  = q >> 3;
            const int ch   = q & 7;
            const float* base;
            int row0;
            if      (tile == 0) { base = g_xhi;  row0 = m0; }
            else if (tile == 1) { base = g_whiT; row0 = n0; }
            else                { base = g_wloT; row0 = n0; }
            const float* src = base + (size_t)(row0 + row) * DIM + kof + ch * 4;
            const uint32_t dst = sb + (uint32_t)(tile * (TILE_F * 4) + row * (ROWPAD * 4) + ch * 16);
            CPA16(dst, src);
        }
        CPA_COMMIT();
    };

    issue_stage(0, 0);

    for (int kt = 0; kt < KT; kt++) {
        const int s = kt & 1;
        if (kt + 1 < KT) { issue_stage(kt + 1, s ^ 1); CPA_WAIT1(); }
        else             { CPA_WAIT0(); }
        __syncthreads();

        const float* sAh = sm + s * STAGE_F;
        const float* sBh = sAh + TILE_F;
        const float* sBl = sBh + TILE_F;

        #pragma unroll
        for (int ks = 0; ks < 4; ks++) {
            const int k0 = ks * 8 + laneq;

            float ah[4][4];
            #pragma unroll
            for (int i = 0; i < 4; i++) {
                const int r = (m0w + i * 16 + lane4) * ROWPAD + k0;
                ah[i][0] = sAh[r];
                ah[i][1] = sAh[r + 8 * ROWPAD];
                ah[i][2] = sAh[r + 4];
                ah[i][3] = sAh[r + 8 * ROWPAD + 4];
            }
            float bh[4][2], bl[4][2];
            #pragma unroll
            for (int j = 0; j < 4; j++) {
                const int rc = (n0w + j * 8 + lane4) * ROWPAD + k0;
                bh[j][0] = sBh[rc];
                bh[j][1] = sBh[rc + 4];
                bl[j][0] = sBl[rc];
                bl[j][1] = sBl[rc + 4];
            }
            #pragma unroll
            for (int i = 0; i < 4; i++)
                #pragma unroll
                for (int j = 0; j < 4; j++) {
                    mma_tf32(c[i][j], ah[i], bh[j]);
                    mma_tf32(c[i][j], ah[i], bl[j]);
                }
        }
        __syncthreads();
    }

    // epilogue: += x_init, store h
    #pragma unroll
    for (int i = 0; i < 4; i++) {
        const int row = m0 + m0w + i * 16 + lane4;
        #pragma unroll
        for (int j = 0; j < 4; j++) {
            const int col = n0 + n0w + j * 8 + laneq * 2;
            const size_t o0 = (size_t)row * DIM + col;
            const size_t o1 = (size_t)(row + 8) * DIM + col;
            const float2 x0 = *(const float2*)(x_init + o0);
            const float2 x1 = *(const float2*)(x_init + o1);
            float2 v0, v1;
            v0.x = c[i][j][0] + x0.x;
            v0.y = c[i][j][1] + x0.y;
            v1.x = c[i][j][2] + x1.x;
            v1.y = c[i][j][3] + x1.y;
            *(float2*)(g_h + o0) = v0;
            *(float2*)(g_h + o1) = v1;
        }
    }
}

// ---------------- stats stage 1: deterministic partial column sums ----------
__global__ __launch_bounds__(256) void stats1_kernel()
{
    const int col = blockIdx.x * 256 + threadIdx.x;
    const int rg  = blockIdx.y;
    const int r0  = rg * 256;
    float s = 0.0f, q = 0.0f;
    const float* p = g_h + (size_t)r0 * DIM + col;
    #pragma unroll 8
    for (int r = 0; r < 256; r++) {
        const float v = p[(size_t)r * DIM];
        s += v;
        q = fmaf(v, v, q);
    }
    g_psum[rg * DIM + col]   = s;
    g_psumsq[rg * DIM + col] = q;
}

// ---------------- stats stage 2: finalize mean / scale ----------------------
__global__ __launch_bounds__(256) void stats2_kernel()
{
    const int col = blockIdx.x * 256 + threadIdx.x;
    float s = 0.0f, q = 0.0f;
    #pragma unroll
    for (int rg = 0; rg < 32; rg++) {
        s += g_psum[rg * DIM + col];
        q += g_psumsq[rg * DIM + col];
    }
    const float inv_n = 1.0f / (float)B_ROWS;
    const float mean  = s * inv_n;
    float var = q * inv_n - mean * mean;
    var = fmaxf(var, 0.0f);
    g_mean[col]  = mean;
    g_scale[col] = 1.0f / (sqrtf(var) + EPS);
}

// ---------------- normalize + sigmoid ---------------------------------------
__global__ __launch_bounds__(256) void final_kernel(float* __restrict__ out)
{
    const int row  = blockIdx.y;
    const int col  = (blockIdx.x * 256 + threadIdx.x) * 4;
    const size_t off = (size_t)row * DIM + col;

    const float4 h  = *(const float4*)(g_h + off);
    const float4 mu = *(const float4*)(g_mean + col);
    const float4 sc = *(const float4*)(g_scale + col);

    float4 o;
    o.x = 1.0f / (1.0f + expf(-(h.x - mu.x) * sc.x));
    o.y = 1.0f / (1.0f + expf(-(h.y - mu.y) * sc.y));
    o.z = 1.0f / (1.0f + expf(-(h.z - mu.z) * sc.z));
    o.w = 1.0f / (1.0f + expf(-(h.w - mu.w) * sc.w));
    *(float4*)(out + off) = o;
}

// ---------------- launcher ---------------------------------------------------
extern "C" void kernel_launch(void* const* d_in, const int* in_sizes, int n_in,
                              void* d_out, int out_size)
{
    const float* x   = (const float*)d_in[0];
    const float* xi  = (const float*)d_in[1];
    const float* tw  = (const float*)d_in[2];
    const float* bbw = (const float*)d_in[3];
    float* out = (float*)d_out;

    cudaFuncSetAttribute(gemm_mma_kernel,
                         cudaFuncAttributeMaxDynamicSharedMemorySize, DYN_SMEM);

    split_x_kernel<<<(B_ROWS * DIM) / (256 * 4), 256>>>((const float4*)x);
    split_w_kernel<<<dim3(DIM / 32, DIM / 32), 256>>>(tw, bbw);
    gemm_mma_kernel<<<dim3(NT, MT), 256, DYN_SMEM>>>(xi);
    stats1_kernel<<<dim3(DIM / 256, 32), 256>>>();
    stats2_kernel<<<DIM / 256, 256>>>();
    final_kernel<<<dim3(DIM / (256 * 4), B_ROWS), 256>>>(out);
}

// round 5
// speedup vs baseline: 2.4580x; 1.2497x over previous
#include <cuda_runtime.h>
#include <cuda_bf16.h>
#include <cstdint>
#include <math.h>

#define DIM    4096
#define B_ROWS 8192
#define EPS    1e-6f

// GEMM tiling
#define BM 128
#define BN 128
#define BK 32
#define NT 32                 // column tiles
#define MT 64                 // row tiles
#define ROWB 80               // bytes per smem row (32 bf16 = 64B data + 16B pad)
#define TILE_B (128 * ROWB)   // 10240 bytes per operand tile
#define STAGE_B (4 * TILE_B)  // Ah, Al, Bh, Bl = 40960 bytes
#define DYN_SMEM (2 * STAGE_B)  // 81920 -> 2 CTAs/SM

// ---------------- scratch (device globals; no runtime allocation) ----------
__device__ __nv_bfloat16 g_xh[(size_t)B_ROWS * DIM];
__device__ __nv_bfloat16 g_xl[(size_t)B_ROWS * DIM];
__device__ __nv_bfloat16 g_whT[(size_t)DIM * DIM];   // W^T hi: [n][k]
__device__ __nv_bfloat16 g_wlT[(size_t)DIM * DIM];   // W^T lo
__device__ float g_h[(size_t)B_ROWS * DIM];
__device__ float g_psum[32 * DIM];
__device__ float g_psumsq[32 * DIM];
__device__ float g_mean[DIM];
__device__ float g_scale[DIM];

// ---------------- helpers ---------------------------------------------------
__device__ __forceinline__ uint32_t smem_u32(const void* p) {
    uint32_t a;
    asm("{ .reg .u64 t; cvta.to.shared.u64 t, %1; cvt.u32.u64 %0, t; }"
        : "=r"(a) : "l"(p));
    return a;
}

__device__ __forceinline__ uint32_t pk2(__nv_bfloat16 a, __nv_bfloat16 b) {
    return (uint32_t)__bfloat16_as_ushort(a) | ((uint32_t)__bfloat16_as_ushort(b) << 16);
}

#define CPA16(dst, src) \
    asm volatile("cp.async.cg.shared.global [%0], [%1], 16;" :: "r"(dst), "l"(src) : "memory")
#define CPA_COMMIT() asm volatile("cp.async.commit_group;" ::: "memory")
#define CPA_WAIT1()  asm volatile("cp.async.wait_group 1;" ::: "memory")
#define CPA_WAIT0()  asm volatile("cp.async.wait_group 0;" ::: "memory")

#define LDSM4(r0, r1, r2, r3, addr) \
    asm volatile("ldmatrix.sync.aligned.m8n8.x4.shared.b16 {%0,%1,%2,%3}, [%4];" \
        : "=r"(r0), "=r"(r1), "=r"(r2), "=r"(r3) : "r"(addr))

__device__ __forceinline__ void mma_bf16(float* c, const uint32_t* a, const uint32_t* b) {
    asm volatile(
        "mma.sync.aligned.m16n8k16.row.col.f32.bf16.bf16.f32 "
        "{%0,%1,%2,%3}, {%4,%5,%6,%7}, {%8,%9}, {%0,%1,%2,%3};"
        : "+f"(c[0]), "+f"(c[1]), "+f"(c[2]), "+f"(c[3])
        : "r"(a[0]), "r"(a[1]), "r"(a[2]), "r"(a[3]),
          "r"(b[0]), "r"(b[1]));
}

// ---------------- prologue 1: split x into bf16 hi/lo -----------------------
__global__ __launch_bounds__(256) void split_x_kernel(const float4* __restrict__ x)
{
    const size_t i = (size_t)blockIdx.x * 256 + threadIdx.x;
    const float4 v = x[i];
    const __nv_bfloat16 hx = __float2bfloat16(v.x);
    const __nv_bfloat16 hy = __float2bfloat16(v.y);
    const __nv_bfloat16 hz = __float2bfloat16(v.z);
    const __nv_bfloat16 hw = __float2bfloat16(v.w);
    const __nv_bfloat16 lx = __float2bfloat16(v.x - __bfloat162float(hx));
    const __nv_bfloat16 ly = __float2bfloat16(v.y - __bfloat162float(hy));
    const __nv_bfloat16 lz = __float2bfloat16(v.z - __bfloat162float(hz));
    const __nv_bfloat16 lw = __float2bfloat16(v.w - __bfloat162float(hw));
    uint2 H, L;
    H.x = pk2(hx, hy); H.y = pk2(hz, hw);
    L.x = pk2(lx, ly); L.y = pk2(lz, lw);
    ((uint2*)g_xh)[i] = H;
    ((uint2*)g_xl)[i] = L;
}

// ---------------- prologue 2: build W^T (masked, squared diag), split hi/lo -
__global__ __launch_bounds__(256) void split_w_kernel(
    const float* __restrict__ tw, const float* __restrict__ bbw)
{
    __shared__ float sw[32][33];
    const int tx = threadIdx.x & 31;
    const int ty = threadIdx.x >> 5;           // 0..7
    const int k0 = blockIdx.y * 32;
    const int n0 = blockIdx.x * 32;

    #pragma unroll
    for (int r = 0; r < 4; r++) {
        const int k = k0 + ty + r * 8;
        const int n = n0 + tx;
        const int kb = k >> 6, nb = n >> 6;
        float w = 0.0f;
        if (kb == nb)      { const float t = tw[(size_t)k * DIM + n]; w = t * t; }
        else if (kb < nb)  { w = bbw[(size_t)k * DIM + n]; }
        sw[ty + r * 8][tx] = w;
    }
    __syncthreads();
    #pragma unroll
    for (int r = 0; r < 4; r++) {
        const int n = n0 + ty + r * 8;
        const int k = k0 + tx;
        const float w = sw[tx][ty + r * 8];
        const __nv_bfloat16 h = __float2bfloat16(w);
        const __nv_bfloat16 l = __float2bfloat16(w - __bfloat162float(h));
        g_whT[(size_t)n * DIM + k] = h;
        g_wlT[(size_t)n * DIM + k] = l;
    }
}

// ---------------- bf16 3-pass mma.sync GEMM: h = x @ W + x_init -------------
// Grid (NT, MT). CTA 128x128, BK=32, 2-stage cp.async pipeline, 2 CTAs/SM.
// Warp (wid>>2 = m half, wid&3 = n quarter): 64x32 warp tile.
// Passes: c += Ah*Bh ; c += Al*Bh ; c += Ah*Bl    (Al*Bl dropped, ~2^-18)
__global__ __launch_bounds__(256, 2) void gemm_mma_kernel(const float* __restrict__ x_init)
{
    extern __shared__ char smc[];
    const uint32_t smb = smem_u32(smc);

    const int tid = threadIdx.x;
    const int wid = tid >> 5;
    const int lid = tid & 31;
    const int lane4 = lid >> 2;     // 0..7
    const int laneq = lid & 3;      // 0..3

    const int nt = (NT - 1) - blockIdx.x;   // heavy tiles first
    const int mt = blockIdx.y;
    const int m0 = mt * BM;
    const int n0 = nt * BN;
    const int KT = (nt + 1) * 4;    // k-tiles of 32

    const int m0w = (wid >> 2) * 64;
    const int n0w = (wid & 3) * 32;

    float c[4][4][4];
    #pragma unroll
    for (int i = 0; i < 4; i++)
        #pragma unroll
        for (int j = 0; j < 4; j++)
            #pragma unroll
            for (int q = 0; q < 4; q++)
                c[i][j][q] = 0.0f;

    // producer: 8 cp.async (16B) per thread per stage.
    // idx -> tile (0:Ah 1:Al 2:Bh 3:Bl), row (0..127), chunk (0..3)
    auto issue_stage = [&](int kt, int s) {
        const int kof = kt * BK;
        const uint32_t sb = smb + (uint32_t)s * STAGE_B;
        #pragma unroll
        for (int it = 0; it < 8; it++) {
            const int idx  = tid + it * 256;
            const int tile = idx >> 9;
            const int row  = (idx >> 2) & 127;
            const int ch   = idx & 3;
            const __nv_bfloat16* base;
            int row0;
            if      (tile == 0) { base = g_xh;  row0 = m0; }
            else if (tile == 1) { base = g_xl;  row0 = m0; }
            else if (tile == 2) { base = g_whT; row0 = n0; }
            else                { base = g_wlT; row0 = n0; }
            const __nv_bfloat16* src = base + (size_t)(row0 + row) * DIM + kof + ch * 8;
            const uint32_t dst = sb + (uint32_t)(tile * TILE_B + row * ROWB + ch * 16);
            CPA16(dst, src);
        }
        CPA_COMMIT();
    };

    // per-thread ldmatrix offset components (byte offsets within a tile)
    const int L = lid;
    const uint32_t a_off = (uint32_t)((m0w + (L & 15)) * ROWB + (L >> 4) * 16);
    const uint32_t b_off = (uint32_t)((n0w + ((L >> 4) & 1) * 8 + (L & 7)) * ROWB
                                      + ((L >> 3) & 1) * 16);

    issue_stage(0, 0);

    for (int kt = 0; kt < KT; kt++) {
        const int s = kt & 1;
        if (kt + 1 < KT) { issue_stage(kt + 1, s ^ 1); CPA_WAIT1(); }
        else             { CPA_WAIT0(); }
        __syncthreads();

        const uint32_t sb  = smb + (uint32_t)s * STAGE_B;
        const uint32_t sAh = sb;
        const uint32_t sAl = sb + TILE_B;
        const uint32_t sBh = sb + 2 * TILE_B;
        const uint32_t sBl = sb + 3 * TILE_B;

        #pragma unroll
        for (int ks = 0; ks < 2; ks++) {
            const uint32_t ko = (uint32_t)ks * 32;

            // B fragments: bh[j][2], bl[j][2] via 2 ldmatrix.x4 each
            uint32_t bh[4][2], bl[4][2];
            #pragma unroll
            for (int jp = 0; jp < 2; jp++) {
                const uint32_t bo = b_off + (uint32_t)jp * 16 * ROWB + ko;
                LDSM4(bh[jp*2][0], bh[jp*2][1], bh[jp*2+1][0], bh[jp*2+1][1], sBh + bo);
                LDSM4(bl[jp*2][0], bl[jp*2][1], bl[jp*2+1][0], bl[jp*2+1][1], sBl + bo);
            }
            // stream A fragments per i (keeps regs under 128)
            #pragma unroll
            for (int i = 0; i < 4; i++) {
                const uint32_t ao = a_off + (uint32_t)i * 16 * ROWB + ko;
                uint32_t ah[4], al[4];
                LDSM4(ah[0], ah[1], ah[2], ah[3], sAh + ao);
                LDSM4(al[0], al[1], al[2], al[3], sAl + ao);
                #pragma unroll
                for (int j = 0; j < 4; j++) {
                    mma_bf16(c[i][j], ah, bh[j]);
                    mma_bf16(c[i][j], al, bh[j]);
                    mma_bf16(c[i][j], ah, bl[j]);
                }
            }
        }
        __syncthreads();
    }

    // epilogue: += x_init, store h
    #pragma unroll
    for (int i = 0; i < 4; i++) {
        const int row = m0 + m0w + i * 16 + lane4;
        #pragma unroll
        for (int j = 0; j < 4; j++) {
            const int col = n0 + n0w + j * 8 + laneq * 2;
            const size_t o0 = (size_t)row * DIM + col;
            const size_t o1 = (size_t)(row + 8) * DIM + col;
            const float2 x0 = *(const float2*)(x_init + o0);
            const float2 x1 = *(const float2*)(x_init + o1);
            float2 v0, v1;
            v0.x = c[i][j][0] + x0.x;
            v0.y = c[i][j][1] + x0.y;
            v1.x = c[i][j][2] + x1.x;
            v1.y = c[i][j][3] + x1.y;
            *(float2*)(g_h + o0) = v0;
            *(float2*)(g_h + o1) = v1;
        }
    }
}

// ---------------- stats stage 1: deterministic partial column sums ----------
// thread handles 4 columns (float4) over 256 rows; fixed slot -> deterministic
__global__ __launch_bounds__(256) void stats1_kernel()
{
    const int c4  = blockIdx.x * 256 + threadIdx.x;   // 0..1023
    const int col = c4 * 4;
    const int rg  = blockIdx.y;                       // 0..31
    const int r0  = rg * 256;
    float4 s = {0.f, 0.f, 0.f, 0.f};
    float4 q = {0.f, 0.f, 0.f, 0.f};
    const float* p = g_h + (size_t)r0 * DIM + col;
    #pragma unroll 4
    for (int r = 0; r < 256; r++) {
        const float4 v = *(const float4*)(p + (size_t)r * DIM);
        s.x += v.x; q.x = fmaf(v.x, v.x, q.x);
        s.y += v.y; q.y = fmaf(v.y, v.y, q.y);
        s.z += v.z; q.z = fmaf(v.z, v.z, q.z);
        s.w += v.w; q.w = fmaf(v.w, v.w, q.w);
    }
    *(float4*)(g_psum + rg * DIM + col)   = s;
    *(float4*)(g_psumsq + rg * DIM + col) = q;
}

// ---------------- stats stage 2: finalize mean / scale ----------------------
__global__ __launch_bounds__(256) void stats2_kernel()
{
    const int col = blockIdx.x * 256 + threadIdx.x;
    float s = 0.0f, q = 0.0f;
    #pragma unroll
    for (int rg = 0; rg < 32; rg++) {
        s += g_psum[rg * DIM + col];
        q += g_psumsq[rg * DIM + col];
    }
    const float inv_n = 1.0f / (float)B_ROWS;
    const float mean  = s * inv_n;
    float var = q * inv_n - mean * mean;
    var = fmaxf(var, 0.0f);
    g_mean[col]  = mean;
    g_scale[col] = 1.0f / (sqrtf(var) + EPS);
}

// ---------------- normalize + sigmoid ---------------------------------------
__global__ __launch_bounds__(256) void final_kernel(float* __restrict__ out)
{
    const int row  = blockIdx.y;
    const int col  = (blockIdx.x * 256 + threadIdx.x) * 4;
    const size_t off = (size_t)row * DIM + col;

    const float4 h  = *(const float4*)(g_h + off);
    const float4 mu = *(const float4*)(g_mean + col);
    const float4 sc = *(const float4*)(g_scale + col);

    float4 o;
    o.x = 1.0f / (1.0f + expf(-(h.x - mu.x) * sc.x));
    o.y = 1.0f / (1.0f + expf(-(h.y - mu.y) * sc.y));
    o.z = 1.0f / (1.0f + expf(-(h.z - mu.z) * sc.z));
    o.w = 1.0f / (1.0f + expf(-(h.w - mu.w) * sc.w));
    *(float4*)(out + off) = o;
}

// ---------------- launcher ---------------------------------------------------
extern "C" void kernel_launch(void* const* d_in, const int* in_sizes, int n_in,
                              void* d_out, int out_size)
{
    const float* x   = (const float*)d_in[0];
    const float* xi  = (const float*)d_in[1];
    const float* tw  = (const float*)d_in[2];
    const float* bbw = (const float*)d_in[3];
    float* out = (float*)d_out;

    cudaFuncSetAttribute(gemm_mma_kernel,
                         cudaFuncAttributeMaxDynamicSharedMemorySize, DYN_SMEM);

    split_x_kernel<<<(B_ROWS * DIM) / (256 * 4), 256>>>((const float4*)x);
    split_w_kernel<<<dim3(DIM / 32, DIM / 32), 256>>>(tw, bbw);
    gemm_mma_kernel<<<dim3(NT, MT), 256, DYN_SMEM>>>(xi);
    stats1_kernel<<<dim3(4, 32), 256>>>();
    stats2_kernel<<<DIM / 256, 256>>>();
    final_kernel<<<dim3(DIM / (256 * 4), B_ROWS), 256>>>(out);
}

// round 6
// speedup vs baseline: 3.4673x; 1.4106x over previous
#include <cuda_runtime.h>
#include <cuda_fp16.h>
#include <cstdint>
#include <math.h>

#define DIM    4096
#define B_ROWS 8192
#define EPS    1e-6f

// GEMM tiling
#define BM 128
#define BN 128
#define BK 32
#define NT 32                 // column tiles
#define MT 64                 // row tiles
#define ROWB 80               // bytes per smem row (32 fp16 = 64B data + 16B pad)
#define TILE_B (128 * ROWB)   // 10240 bytes per operand tile
#define STAGE_B (3 * TILE_B)  // Ah, Bh, Bl = 30720 bytes
#define DYN_SMEM (2 * STAGE_B)  // 61440 -> 2 CTAs/SM

// ---------------- scratch (device globals; no runtime allocation) ----------
__device__ __half g_xh[(size_t)B_ROWS * DIM];        // fp16-rounded x
__device__ __half g_whT[(size_t)DIM * DIM];          // W^T hi: [n][k]
__device__ __half g_wlT[(size_t)DIM * DIM];          // W^T lo (fp16 residual)
__device__ float g_h[(size_t)B_ROWS * DIM];
__device__ float g_psum[128 * DIM];
__device__ float g_psumsq[128 * DIM];
__device__ float g_mean[DIM];
__device__ float g_scale[DIM];

// ---------------- helpers ---------------------------------------------------
__device__ __forceinline__ uint32_t smem_u32(const void* p) {
    uint32_t a;
    asm("{ .reg .u64 t; cvta.to.shared.u64 t, %1; cvt.u32.u64 %0, t; }"
        : "=r"(a) : "l"(p));
    return a;
}

__device__ __forceinline__ uint32_t pk2(__half a, __half b) {
    return (uint32_t)__half_as_ushort(a) | ((uint32_t)__half_as_ushort(b) << 16);
}

#define CPA16(dst, src) \
    asm volatile("cp.async.cg.shared.global [%0], [%1], 16;" :: "r"(dst), "l"(src) : "memory")
#define CPA_COMMIT() asm volatile("cp.async.commit_group;" ::: "memory")
#define CPA_WAIT1()  asm volatile("cp.async.wait_group 1;" ::: "memory")
#define CPA_WAIT0()  asm volatile("cp.async.wait_group 0;" ::: "memory")

#define LDSM4(r0, r1, r2, r3, addr) \
    asm volatile("ldmatrix.sync.aligned.m8n8.x4.shared.b16 {%0,%1,%2,%3}, [%4];" \
        : "=r"(r0), "=r"(r1), "=r"(r2), "=r"(r3) : "r"(addr))

__device__ __forceinline__ void mma_fp16(float* c, const uint32_t* a, const uint32_t* b) {
    asm volatile(
        "mma.sync.aligned.m16n8k16.row.col.f32.f16.f16.f32 "
        "{%0,%1,%2,%3}, {%4,%5,%6,%7}, {%8,%9}, {%0,%1,%2,%3};"
        : "+f"(c[0]), "+f"(c[1]), "+f"(c[2]), "+f"(c[3])
        : "r"(a[0]), "r"(a[1]), "r"(a[2]), "r"(a[3]),
          "r"(b[0]), "r"(b[1]));
}

// ---------------- prologue 1: round x to fp16 -------------------------------
__global__ __launch_bounds__(256) void split_x_kernel(const float4* __restrict__ x)
{
    const size_t i = (size_t)blockIdx.x * 256 + threadIdx.x;
    const float4 v = x[i];
    uint2 H;
    H.x = pk2(__float2half_rn(v.x), __float2half_rn(v.y));
    H.y = pk2(__float2half_rn(v.z), __float2half_rn(v.w));
    ((uint2*)g_xh)[i] = H;
}

// ---------------- prologue 2: build W^T (masked, squared diag), split hi/lo -
__global__ __launch_bounds__(256) void split_w_kernel(
    const float* __restrict__ tw, const float* __restrict__ bbw)
{
    __shared__ float sw[32][33];
    const int tx = threadIdx.x & 31;
    const int ty = threadIdx.x >> 5;           // 0..7
    const int k0 = blockIdx.y * 32;
    const int n0 = blockIdx.x * 32;

    #pragma unroll
    for (int r = 0; r < 4; r++) {
        const int k = k0 + ty + r * 8;
        const int n = n0 + tx;
        const int kb = k >> 6, nb = n >> 6;
        float w = 0.0f;
        if (kb == nb)      { const float t = tw[(size_t)k * DIM + n]; w = t * t; }
        else if (kb < nb)  { w = bbw[(size_t)k * DIM + n]; }
        sw[ty + r * 8][tx] = w;
    }
    __syncthreads();
    #pragma unroll
    for (int r = 0; r < 4; r++) {
        const int n = n0 + ty + r * 8;
        const int k = k0 + tx;
        const float w = sw[tx][ty + r * 8];
        const __half h = __float2half_rn(w);
        const __half l = __float2half_rn(w - __half2float(h));
        g_whT[(size_t)n * DIM + k] = h;
        g_wlT[(size_t)n * DIM + k] = l;
    }
}

// ---------------- fp16 2-pass mma.sync GEMM: h = x @ W + x_init -------------
// Grid (NT, MT). CTA 128x128, BK=32, 2-stage cp.async pipeline, 2 CTAs/SM.
// Warp (wid>>2 = m half, wid&3 = n quarter): 64x32 warp tile.
// Passes: c += Ah*Bh ; c += Ah*Bl   (x residual dropped; rel err ~6e-5 measured-equiv)
__global__ __launch_bounds__(256, 2) void gemm_mma_kernel(const float* __restrict__ x_init)
{
    extern __shared__ char smc[];
    const uint32_t smb = smem_u32(smc);

    const int tid = threadIdx.x;
    const int wid = tid >> 5;
    const int lid = tid & 31;
    const int lane4 = lid >> 2;     // 0..7
    const int laneq = lid & 3;      // 0..3

    const int nt = (NT - 1) - blockIdx.x;   // heavy tiles first
    const int mt = blockIdx.y;
    const int m0 = mt * BM;
    const int n0 = nt * BN;
    const int KT = (nt + 1) * 4;    // k-tiles of 32

    const int m0w = (wid >> 2) * 64;
    const int n0w = (wid & 3) * 32;

    float c[4][4][4];
    #pragma unroll
    for (int i = 0; i < 4; i++)
        #pragma unroll
        for (int j = 0; j < 4; j++)
            #pragma unroll
            for (int q = 0; q < 4; q++)
                c[i][j][q] = 0.0f;

    // producer: 6 cp.async (16B) per thread per stage.
    // idx -> tile (0:Ah 1:Bh 2:Bl), row (0..127), chunk (0..3)
    auto issue_stage = [&](int kt, int s) {
        const int kof = kt * BK;
        const uint32_t sb = smb + (uint32_t)s * STAGE_B;
        #pragma unroll
        for (int it = 0; it < 6; it++) {
            const int idx  = tid + it * 256;
            const int tile = idx >> 9;
            const int row  = (idx >> 2) & 127;
            const int ch   = idx & 3;
            const __half* base;
            int row0;
            if      (tile == 0) { base = g_xh;  row0 = m0; }
            else if (tile == 1) { base = g_whT; row0 = n0; }
            else                { base = g_wlT; row0 = n0; }
            const __half* src = base + (size_t)(row0 + row) * DIM + kof + ch * 8;
            const uint32_t dst = sb + (uint32_t)(tile * TILE_B + row * ROWB + ch * 16);
            CPA16(dst, src);
        }
        CPA_COMMIT();
    };

    // per-thread ldmatrix offset components (byte offsets within a tile)
    const int L = lid;
    const uint32_t a_off = (uint32_t)((m0w + (L & 15)) * ROWB + (L >> 4) * 16);
    const uint32_t b_off = (uint32_t)((n0w + ((L >> 4) & 1) * 8 + (L & 7)) * ROWB
                                      + ((L >> 3) & 1) * 16);

    issue_stage(0, 0);

    for (int kt = 0; kt < KT; kt++) {
        const int s = kt & 1;
        if (kt + 1 < KT) { issue_stage(kt + 1, s ^ 1); CPA_WAIT1(); }
        else             { CPA_WAIT0(); }
        __syncthreads();

        const uint32_t sb  = smb + (uint32_t)s * STAGE_B;
        const uint32_t sAh = sb;
        const uint32_t sBh = sb + TILE_B;
        const uint32_t sBl = sb + 2 * TILE_B;

        #pragma unroll
        for (int ks = 0; ks < 2; ks++) {
            const uint32_t ko = (uint32_t)ks * 32;

            // B fragments: bh[j][2], bl[j][2] via 2 ldmatrix.x4 each
            uint32_t bh[4][2], bl[4][2];
            #pragma unroll
            for (int jp = 0; jp < 2; jp++) {
                const uint32_t bo = b_off + (uint32_t)jp * 16 * ROWB + ko;
                LDSM4(bh[jp*2][0], bh[jp*2][1], bh[jp*2+1][0], bh[jp*2+1][1], sBh + bo);
                LDSM4(bl[jp*2][0], bl[jp*2][1], bl[jp*2+1][0], bl[jp*2+1][1], sBl + bo);
            }
            // stream A fragments per i
            #pragma unroll
            for (int i = 0; i < 4; i++) {
                const uint32_t ao = a_off + (uint32_t)i * 16 * ROWB + ko;
                uint32_t ah[4];
                LDSM4(ah[0], ah[1], ah[2], ah[3], sAh + ao);
                #pragma unroll
                for (int j = 0; j < 4; j++) {
                    mma_fp16(c[i][j], ah, bh[j]);
                    mma_fp16(c[i][j], ah, bl[j]);
                }
            }
        }
        __syncthreads();
    }

    // epilogue: += x_init, store h
    #pragma unroll
    for (int i = 0; i < 4; i++) {
        const int row = m0 + m0w + i * 16 + lane4;
        #pragma unroll
        for (int j = 0; j < 4; j++) {
            const int col = n0 + n0w + j * 8 + laneq * 2;
            const size_t o0 = (size_t)row * DIM + col;
            const size_t o1 = (size_t)(row + 8) * DIM + col;
            const float2 x0 = *(const float2*)(x_init + o0);
            const float2 x1 = *(const float2*)(x_init + o1);
            float2 v0, v1;
            v0.x = c[i][j][0] + x0.x;
            v0.y = c[i][j][1] + x0.y;
            v1.x = c[i][j][2] + x1.x;
            v1.y = c[i][j][3] + x1.y;
            *(float2*)(g_h + o0) = v0;
            *(float2*)(g_h + o1) = v1;
        }
    }
}

// ---------------- stats stage 1: deterministic partial column sums ----------
// grid (4, 128): thread owns 4 columns (float4) over 64 rows; fixed slots.
__global__ __launch_bounds__(256) void stats1_kernel()
{
    const int c4  = blockIdx.x * 256 + threadIdx.x;   // 0..1023
    const int col = c4 * 4;
    const int rg  = blockIdx.y;                       // 0..127
    const int r0  = rg * 64;
    float4 s = {0.f, 0.f, 0.f, 0.f};
    float4 q = {0.f, 0.f, 0.f, 0.f};
    const float* p = g_h + (size_t)r0 * DIM + col;
    #pragma unroll 4
    for (int r = 0; r < 64; r++) {
        const float4 v = *(const float4*)(p + (size_t)r * DIM);
        s.x += v.x; q.x = fmaf(v.x, v.x, q.x);
        s.y += v.y; q.y = fmaf(v.y, v.y, q.y);
        s.z += v.z; q.z = fmaf(v.z, v.z, q.z);
        s.w += v.w; q.w = fmaf(v.w, v.w, q.w);
    }
    *(float4*)(g_psum + rg * DIM + col)   = s;
    *(float4*)(g_psumsq + rg * DIM + col) = q;
}

// ---------------- stats stage 2: finalize mean / scale ----------------------
__global__ __launch_bounds__(256) void stats2_kernel()
{
    const int col = blockIdx.x * 256 + threadIdx.x;
    float s = 0.0f, q = 0.0f;
    #pragma unroll 8
    for (int rg = 0; rg < 128; rg++) {
        s += g_psum[rg * DIM + col];
        q += g_psumsq[rg * DIM + col];
    }
    const float inv_n = 1.0f / (float)B_ROWS;
    const float mean  = s * inv_n;
    float var = q * inv_n - mean * mean;
    var = fmaxf(var, 0.0f);
    g_mean[col]  = mean;
    g_scale[col] = 1.0f / (sqrtf(var) + EPS);
}

// ---------------- normalize + sigmoid ---------------------------------------
__global__ __launch_bounds__(256) void final_kernel(float* __restrict__ out)
{
    const int row  = blockIdx.y;
    const int col  = (blockIdx.x * 256 + threadIdx.x) * 4;
    const size_t off = (size_t)row * DIM + col;

    const float4 h  = *(const float4*)(g_h + off);
    const float4 mu = *(const float4*)(g_mean + col);
    const float4 sc = *(const float4*)(g_scale + col);

    float4 o;
    o.x = 1.0f / (1.0f + expf(-(h.x - mu.x) * sc.x));
    o.y = 1.0f / (1.0f + expf(-(h.y - mu.y) * sc.y));
    o.z = 1.0f / (1.0f + expf(-(h.z - mu.z) * sc.z));
    o.w = 1.0f / (1.0f + expf(-(h.w - mu.w) * sc.w));
    *(float4*)(out + off) = o;
}

// ---------------- launcher ---------------------------------------------------
extern "C" void kernel_launch(void* const* d_in, const int* in_sizes, int n_in,
                              void* d_out, int out_size)
{
    const float* x   = (const float*)d_in[0];
    const float* xi  = (const float*)d_in[1];
    const float* tw  = (const float*)d_in[2];
    const float* bbw = (const float*)d_in[3];
    float* out = (float*)d_out;

    cudaFuncSetAttribute(gemm_mma_kernel,
                         cudaFuncAttributeMaxDynamicSharedMemorySize, DYN_SMEM);

    split_x_kernel<<<(B_ROWS * DIM) / (256 * 4), 256>>>((const float4*)x);
    split_w_kernel<<<dim3(DIM / 32, DIM / 32), 256>>>(tw, bbw);
    gemm_mma_kernel<<<dim3(NT, MT), 256, DYN_SMEM>>>(xi);
    stats1_kernel<<<dim3(4, 128), 256>>>();
    stats2_kernel<<<DIM / 256, 256>>>();
    final_kernel<<<dim3(DIM / (256 * 4), B_ROWS), 256>>>(out);
}